// round 1
// baseline (speedup 1.0000x reference)
#include <cuda_runtime.h>
#include <cstdint>

#define NN 100000
#define NE 1600000
#define DIM 128

// Scratch (allocation-free rule: __device__ globals)
__device__ float g_agg[NN * DIM];   // 51.2 MB aggregation buffer
__device__ float g_h1[NN * DIM];    // layer-1 activations
__device__ float g_h2[NN * DIM];    // layer-2 activations
__device__ float g_deg[NN];         // degree -> deg_inv (in place)

// ---------------------------------------------------------------------------
// zero a float buffer (n divisible by 4), grid-stride float4
// ---------------------------------------------------------------------------
__global__ void k_zero(float* __restrict__ p, int n4) {
    int i = blockIdx.x * blockDim.x + threadIdx.x;
    int stride = gridDim.x * blockDim.x;
    float4 z = make_float4(0.f, 0.f, 0.f, 0.f);
    for (int j = i; j < n4; j += stride) ((float4*)p)[j] = z;
}

// ---------------------------------------------------------------------------
// degree count: one thread per edge, atomicAdd 1.0 at dst
// ---------------------------------------------------------------------------
__global__ void k_deg(const int* __restrict__ dst, float* __restrict__ deg) {
    int e = blockIdx.x * blockDim.x + threadIdx.x;
    if (e < NE) atomicAdd(&deg[dst[e]], 1.0f);
}

__global__ void k_deg_inv(float* __restrict__ deg) {
    int i = blockIdx.x * blockDim.x + threadIdx.x;
    if (i < NN) {
        float v = deg[i];
        deg[i] = (v > 0.f) ? (1.0f / v) : 0.0f;
    }
}

// ---------------------------------------------------------------------------
// scatter: one warp per edge. Each lane moves 16B (float4) of the 512B row.
// agg[dst] += in[src] via vector reduction (red.global.add.v4.f32, sm_90+).
// ---------------------------------------------------------------------------
__global__ void k_scatter(const float* __restrict__ in,
                          const int* __restrict__ src,
                          const int* __restrict__ dst) {
    int w    = (blockIdx.x * blockDim.x + threadIdx.x) >> 5;
    int lane = threadIdx.x & 31;
    if (w >= NE) return;
    int s = __ldg(src + w);
    int d = __ldg(dst + w);
    float4 v = __ldg(((const float4*)(in + (size_t)s * DIM)) + lane);
    float* o = g_agg + (size_t)d * DIM + lane * 4;
    asm volatile("red.global.add.v4.f32 [%0], {%1, %2, %3, %4};"
                 :: "l"(o), "f"(v.x), "f"(v.y), "f"(v.z), "f"(v.w)
                 : "memory");
}

// ---------------------------------------------------------------------------
// fused SAGE GEMM:
//   out[n,:] = act( (g_agg[n,:] * deg_inv[n]) @ Wl + hin[n,:] @ Wr + b )
//
// Block: 128 threads = (tx 0..15 cols) x (ty 0..7 rows), tile 64 rows x 128
// cols, 8x8 register accumulators per thread. Input tile staged in smem
// (row-major, stride 132 floats so the two ty values within a warp hit
// different banks on the broadcast LDS; 132*4 keeps 16B alignment for STS.128).
// Two phases reuse the same 33KB smem tile: phase 0 = mean/Wl, phase 1 = h/Wr.
// ---------------------------------------------------------------------------
template <bool RELU>
__global__ void __launch_bounds__(128)
k_gemm(const float* __restrict__ hin,
       const float* __restrict__ Wl,
       const float* __restrict__ Wr,
       const float* __restrict__ bias,
       float* __restrict__ out) {
    constexpr int ROWS = 64;
    constexpr int STR  = 132;   // 128 + 4 pad
    __shared__ float s_in[ROWS * STR];

    const int tx = threadIdx.x & 15;   // col group: cols [tx*8, tx*8+8)
    const int ty = threadIdx.x >> 4;   // row group: rows {ty, ty+8, ..., ty+56}
    const int row0 = blockIdx.x * ROWS;

    float acc[8][8];
#pragma unroll
    for (int i = 0; i < 8; ++i)
#pragma unroll
        for (int j = 0; j < 8; ++j) acc[i][j] = 0.f;

#pragma unroll
    for (int phase = 0; phase < 2; ++phase) {
        const float* base = phase ? hin : g_agg;
        const float* W    = phase ? Wr  : Wl;

        __syncthreads();  // previous phase's reads of s_in are done
        // stage 64x128 input tile (apply deg_inv scaling in phase 0)
        for (int t = threadIdx.x; t < ROWS * 32; t += 128) {
            int r  = t >> 5;
            int c4 = t & 31;
            int grow = row0 + r;
            float4 v = make_float4(0.f, 0.f, 0.f, 0.f);
            if (grow < NN) {
                v = __ldg(((const float4*)(base + (size_t)grow * DIM)) + c4);
                if (phase == 0) {
                    float di = __ldg(g_deg + grow);
                    v.x *= di; v.y *= di; v.z *= di; v.w *= di;
                }
            }
            *(float4*)(s_in + r * STR + c4 * 4) = v;
        }
        __syncthreads();

#pragma unroll 4
        for (int k = 0; k < DIM; ++k) {
            float4 w0 = __ldg((const float4*)(W + k * DIM + tx * 8));
            float4 w1 = __ldg((const float4*)(W + k * DIM + tx * 8) + 1);
            float wv[8] = {w0.x, w0.y, w0.z, w0.w, w1.x, w1.y, w1.z, w1.w};
            float sv[8];
#pragma unroll
            for (int i = 0; i < 8; ++i) sv[i] = s_in[(ty + i * 8) * STR + k];
#pragma unroll
            for (int i = 0; i < 8; ++i)
#pragma unroll
                for (int j = 0; j < 8; ++j) acc[i][j] += sv[i] * wv[j];
        }
    }

    // epilogue: + bias, optional ReLU, store
    float4 b0 = __ldg((const float4*)(bias + tx * 8));
    float4 b1 = __ldg((const float4*)(bias + tx * 8) + 1);
    float bv[8] = {b0.x, b0.y, b0.z, b0.w, b1.x, b1.y, b1.z, b1.w};

#pragma unroll
    for (int i = 0; i < 8; ++i) {
        int grow = row0 + ty + i * 8;
        if (grow >= NN) continue;
        float r0[8];
#pragma unroll
        for (int j = 0; j < 8; ++j) {
            float v = acc[i][j] + bv[j];
            if (RELU) v = fmaxf(v, 0.f);
            r0[j] = v;
        }
        float* op = out + (size_t)grow * DIM + tx * 8;
        *(float4*)(op)     = make_float4(r0[0], r0[1], r0[2], r0[3]);
        *(float4*)(op + 4) = make_float4(r0[4], r0[5], r0[6], r0[7]);
    }
}

// ---------------------------------------------------------------------------
// kernel_launch
// inputs (metadata order): t, x, edge_index, W1_l, W1_r, b1, W2_l, W2_r, b2,
//                          W3_l, W3_r, b3
// ---------------------------------------------------------------------------
extern "C" void kernel_launch(void* const* d_in, const int* in_sizes, int n_in,
                              void* d_out, int out_size) {
    const float* x   = (const float*)d_in[1];
    const int*   ei  = (const int*)d_in[2];
    const int*   src = ei;        // edge_index[0]
    const int*   dst = ei + NE;   // edge_index[1]
    const float* W1l = (const float*)d_in[3];
    const float* W1r = (const float*)d_in[4];
    const float* b1  = (const float*)d_in[5];
    const float* W2l = (const float*)d_in[6];
    const float* W2r = (const float*)d_in[7];
    const float* b2  = (const float*)d_in[8];
    const float* W3l = (const float*)d_in[9];
    const float* W3r = (const float*)d_in[10];
    const float* b3  = (const float*)d_in[11];
    float* out = (float*)d_out;

    float *agg, *h1, *h2, *deg;
    cudaGetSymbolAddress((void**)&agg, g_agg);
    cudaGetSymbolAddress((void**)&h1,  g_h1);
    cudaGetSymbolAddress((void**)&h2,  g_h2);
    cudaGetSymbolAddress((void**)&deg, g_deg);

    const int ZB = 2048;                 // grid for grid-stride zero
    const int SCAT_BLOCKS = (NE * 32 + 255) / 256;   // warp per edge
    const int GEMM_BLOCKS = (NN + 63) / 64;

    // degree -> deg_inv
    k_zero<<<128, 256>>>(deg, NN / 4);
    k_deg<<<(NE + 255) / 256, 256>>>(dst, deg);
    k_deg_inv<<<(NN + 255) / 256, 256>>>(deg);

    // layer 1
    k_zero<<<ZB, 256>>>(agg, NN * DIM / 4);
    k_scatter<<<SCAT_BLOCKS, 256>>>(x, src, dst);
    k_gemm<true><<<GEMM_BLOCKS, 128>>>(x, W1l, W1r, b1, h1);

    // layer 2
    k_zero<<<ZB, 256>>>(agg, NN * DIM / 4);
    k_scatter<<<SCAT_BLOCKS, 256>>>(h1, src, dst);
    k_gemm<true><<<GEMM_BLOCKS, 128>>>(h1, W2l, W2r, b2, h2);

    // layer 3 (no relu)
    k_zero<<<ZB, 256>>>(agg, NN * DIM / 4);
    k_scatter<<<SCAT_BLOCKS, 256>>>(h2, src, dst);
    k_gemm<false><<<GEMM_BLOCKS, 128>>>(h2, W3l, W3r, b3, out);
}

// round 2
// speedup vs baseline: 1.1926x; 1.1926x over previous
#include <cuda_runtime.h>
#include <cstdint>

#define NN 100000
#define NE 1600000
#define DIM 128

typedef unsigned long long u64;

// ---------------------------------------------------------------------------
// Scratch (__device__ globals: allocation-free rule)
// ---------------------------------------------------------------------------
__device__ float g_mean[NN * DIM];   // aggregated mean buffer (51.2 MB)
__device__ float g_h1[NN * DIM];
__device__ float g_h2[NN * DIM];
__device__ int   g_deg[NN];
__device__ int   g_rowstart[NN];
__device__ int   g_cursor[NN];
__device__ int   g_csrsrc[NE];
__device__ int   g_bsum[128];

// ---------------------------------------------------------------------------
// f32x2 helpers (Blackwell packed fp32)
// ---------------------------------------------------------------------------
__device__ __forceinline__ u64 pack2(float x, float y) {
    u64 r; asm("mov.b64 %0, {%1, %2};" : "=l"(r) : "f"(x), "f"(y)); return r;
}
__device__ __forceinline__ float2 unpack2(u64 v) {
    float2 p; asm("mov.b64 {%0, %1}, %2;" : "=f"(p.x), "=f"(p.y) : "l"(v)); return p;
}
__device__ __forceinline__ void ffma2(u64& d, u64 a, u64 b) {
    asm("fma.rn.f32x2 %0, %1, %2, %0;" : "+l"(d) : "l"(a), "l"(b));
}

// ---------------------------------------------------------------------------
// small utility kernels
// ---------------------------------------------------------------------------
__global__ void k_zero_int(int* __restrict__ p, int n) {
    int i = blockIdx.x * blockDim.x + threadIdx.x;
    if (i < n) p[i] = 0;
}

__global__ void k_hist(const int* __restrict__ dst) {
    int e = blockIdx.x * blockDim.x + threadIdx.x;
    if (e < NE) atomicAdd(&g_deg[dst[e]], 1);
}

// per-block (1024 elems) sum of degrees
__global__ void k_blocksum() {
    __shared__ int sh[256];
    int base = blockIdx.x * 1024;
    int s = 0;
    for (int j = threadIdx.x; j < 1024; j += 256) {
        int i = base + j;
        if (i < NN) s += g_deg[i];
    }
    sh[threadIdx.x] = s; __syncthreads();
    for (int o = 128; o > 0; o >>= 1) {
        if (threadIdx.x < o) sh[threadIdx.x] += sh[threadIdx.x + o];
        __syncthreads();
    }
    if (threadIdx.x == 0) g_bsum[blockIdx.x] = sh[0];
}

// exclusive scan of block sums (nb <= 128), single block of 128 threads
__global__ void k_bscan(int nb) {
    __shared__ int sh[128];
    int tid = threadIdx.x;
    int v = (tid < nb) ? g_bsum[tid] : 0;
    sh[tid] = v; __syncthreads();
    for (int o = 1; o < 128; o <<= 1) {
        int t = (tid >= o) ? sh[tid - o] : 0;
        __syncthreads();
        sh[tid] += t;
        __syncthreads();
    }
    if (tid < nb) g_bsum[tid] = sh[tid] - v;
}

// final exclusive scan: rowstart + cursor
__global__ void k_scan_final() {
    __shared__ int sh[256];
    int tid = threadIdx.x;
    int base = blockIdx.x * 1024 + tid * 4;
    int v[4]; int s = 0;
#pragma unroll
    for (int j = 0; j < 4; ++j) {
        int i = base + j;
        v[j] = (i < NN) ? g_deg[i] : 0;
        s += v[j];
    }
    sh[tid] = s; __syncthreads();
    for (int o = 1; o < 256; o <<= 1) {
        int t = (tid >= o) ? sh[tid - o] : 0;
        __syncthreads();
        sh[tid] += t;
        __syncthreads();
    }
    int off = g_bsum[blockIdx.x] + sh[tid] - s;
#pragma unroll
    for (int j = 0; j < 4; ++j) {
        int i = base + j;
        if (i < NN) { g_rowstart[i] = off; g_cursor[i] = off; off += v[j]; }
    }
}

// bucket edges by dst
__global__ void k_bucket(const int* __restrict__ src, const int* __restrict__ dst) {
    int e = blockIdx.x * blockDim.x + threadIdx.x;
    if (e < NE) {
        int pos = atomicAdd(&g_cursor[dst[e]], 1);
        g_csrsrc[pos] = src[e];
    }
}

// ---------------------------------------------------------------------------
// pull-mode mean aggregation: one warp per node. Each lane owns 4 dims
// (float4). Indices are loaded cooperatively (32 at a time) and shfl-broadcast.
// Writes the MEAN directly (deg_inv folded in). Every row written: no zeroing.
// ---------------------------------------------------------------------------
__global__ void k_agg(const float* __restrict__ x, float* __restrict__ mean) {
    int w    = (blockIdx.x * blockDim.x + threadIdx.x) >> 5;
    int lane = threadIdx.x & 31;
    if (w >= NN) return;
    int beg = __ldg(g_rowstart + w);
    int d   = __ldg(g_deg + w);

    float4 acc = make_float4(0.f, 0.f, 0.f, 0.f);
    int off = beg, left = d;
    const float4* xv = (const float4*)x;
    while (left > 0) {
        int cnt = min(left, 32);
        int idx = (lane < cnt) ? __ldg(g_csrsrc + off + lane) : 0;
        int j = 0;
        for (; j + 4 <= cnt; j += 4) {
            int s0 = __shfl_sync(0xffffffffu, idx, j);
            int s1 = __shfl_sync(0xffffffffu, idx, j + 1);
            int s2 = __shfl_sync(0xffffffffu, idx, j + 2);
            int s3 = __shfl_sync(0xffffffffu, idx, j + 3);
            float4 v0 = __ldg(xv + (size_t)s0 * 32 + lane);
            float4 v1 = __ldg(xv + (size_t)s1 * 32 + lane);
            float4 v2 = __ldg(xv + (size_t)s2 * 32 + lane);
            float4 v3 = __ldg(xv + (size_t)s3 * 32 + lane);
            acc.x += v0.x + v1.x + v2.x + v3.x;
            acc.y += v0.y + v1.y + v2.y + v3.y;
            acc.z += v0.z + v1.z + v2.z + v3.z;
            acc.w += v0.w + v1.w + v2.w + v3.w;
        }
        for (; j < cnt; ++j) {
            int s = __shfl_sync(0xffffffffu, idx, j);
            float4 v = __ldg(xv + (size_t)s * 32 + lane);
            acc.x += v.x; acc.y += v.y; acc.z += v.z; acc.w += v.w;
        }
        off += cnt; left -= cnt;
    }
    float inv = (d > 0) ? (1.0f / (float)d) : 0.0f;
    acc.x *= inv; acc.y *= inv; acc.z *= inv; acc.w *= inv;
    ((float4*)(mean + (size_t)w * DIM))[lane] = acc;
}

// ---------------------------------------------------------------------------
// fused SAGE GEMM with packed f32x2 FMA:
//   out[n,:] = act( mean[n,:] @ Wl + hin[n,:] @ Wr + b )
//
// Block: 128 threads = (tx 0..15 col-groups of 8) x (ty 0..7 row-groups),
// tile 64 rows x 128 cols, acc = 8 rows x 4 col-pairs of f32x2 per thread.
// Input tile staged in smem with every value DUPLICATED as (v,v) u64 pairs
// so the broadcast FFMA2 operand comes straight from LDS.64. Weight pairs
// (w[2j], w[2j+1]) load as raw u64 from global (L1-resident). Two phases
// (mean/Wl then hin/Wr) reuse the same 65KB smem tile.
// ---------------------------------------------------------------------------
template <bool RELU>
__global__ void __launch_bounds__(128)
k_gemm(const float* __restrict__ mean,
       const float* __restrict__ hin,
       const float* __restrict__ Wl,
       const float* __restrict__ Wr,
       const float* __restrict__ bias,
       float* __restrict__ out) {
    constexpr int ROWS = 64;
    constexpr int STR  = DIM + 2;   // u64 units per row (130): 16B-aligned rows, bank-safe
    extern __shared__ u64 s_dup[];

    const int tx = threadIdx.x & 15;
    const int ty = threadIdx.x >> 4;
    const int row0 = blockIdx.x * ROWS;

    u64 acc[8][4];
#pragma unroll
    for (int i = 0; i < 8; ++i)
#pragma unroll
        for (int j = 0; j < 4; ++j) acc[i][j] = 0ull;

#pragma unroll
    for (int phase = 0; phase < 2; ++phase) {
        const float* base = phase ? hin : mean;
        const float* W    = phase ? Wr  : Wl;

        __syncthreads();
        // stage duplicated tile: thread t handles (row r, float2-chunk c2)
        for (int t = threadIdx.x; t < ROWS * 64; t += 128) {
            int r  = t >> 6;
            int c2 = t & 63;
            int grow = row0 + r;
            float2 v = make_float2(0.f, 0.f);
            if (grow < NN)
                v = __ldg(((const float2*)(base + (size_t)grow * DIM)) + c2);
            ulonglong2 dup = make_ulonglong2(pack2(v.x, v.x), pack2(v.y, v.y));
            *reinterpret_cast<ulonglong2*>(s_dup + r * STR + c2 * 2) = dup;
        }
        __syncthreads();

        const u64* Wp = (const u64*)W;  // pairs: Wp[k*64 + c] = (W[k][2c], W[k][2c+1])
#pragma unroll 4
        for (int k = 0; k < DIM; ++k) {
            u64 w0 = __ldg(Wp + k * 64 + tx * 4 + 0);
            u64 w1 = __ldg(Wp + k * 64 + tx * 4 + 1);
            u64 w2 = __ldg(Wp + k * 64 + tx * 4 + 2);
            u64 w3 = __ldg(Wp + k * 64 + tx * 4 + 3);
            u64 sv[8];
#pragma unroll
            for (int i = 0; i < 8; ++i) sv[i] = s_dup[(ty + 8 * i) * STR + k];
#pragma unroll
            for (int i = 0; i < 8; ++i) {
                ffma2(acc[i][0], sv[i], w0);
                ffma2(acc[i][1], sv[i], w1);
                ffma2(acc[i][2], sv[i], w2);
                ffma2(acc[i][3], sv[i], w3);
            }
        }
    }

    // epilogue
    float4 b0 = __ldg((const float4*)(bias + tx * 8));
    float4 b1 = __ldg((const float4*)(bias + tx * 8) + 1);

#pragma unroll
    for (int i = 0; i < 8; ++i) {
        int grow = row0 + ty + i * 8;
        if (grow >= NN) continue;
        float2 p0 = unpack2(acc[i][0]);
        float2 p1 = unpack2(acc[i][1]);
        float2 p2 = unpack2(acc[i][2]);
        float2 p3 = unpack2(acc[i][3]);
        float4 o0 = make_float4(p0.x + b0.x, p0.y + b0.y, p1.x + b0.z, p1.y + b0.w);
        float4 o1 = make_float4(p2.x + b1.x, p2.y + b1.y, p3.x + b1.z, p3.y + b1.w);
        if (RELU) {
            o0.x = fmaxf(o0.x, 0.f); o0.y = fmaxf(o0.y, 0.f);
            o0.z = fmaxf(o0.z, 0.f); o0.w = fmaxf(o0.w, 0.f);
            o1.x = fmaxf(o1.x, 0.f); o1.y = fmaxf(o1.y, 0.f);
            o1.z = fmaxf(o1.z, 0.f); o1.w = fmaxf(o1.w, 0.f);
        }
        float* op = out + (size_t)grow * DIM + tx * 8;
        *(float4*)(op)     = o0;
        *(float4*)(op + 4) = o1;
    }
}

// ---------------------------------------------------------------------------
// kernel_launch
// inputs: t, x, edge_index, W1_l, W1_r, b1, W2_l, W2_r, b2, W3_l, W3_r, b3
// ---------------------------------------------------------------------------
extern "C" void kernel_launch(void* const* d_in, const int* in_sizes, int n_in,
                              void* d_out, int out_size) {
    const float* x   = (const float*)d_in[1];
    const int*   ei  = (const int*)d_in[2];
    const int*   src = ei;
    const int*   dst = ei + NE;
    const float* W1l = (const float*)d_in[3];
    const float* W1r = (const float*)d_in[4];
    const float* b1  = (const float*)d_in[5];
    const float* W2l = (const float*)d_in[6];
    const float* W2r = (const float*)d_in[7];
    const float* b2  = (const float*)d_in[8];
    const float* W3l = (const float*)d_in[9];
    const float* W3r = (const float*)d_in[10];
    const float* b3  = (const float*)d_in[11];
    float* out = (float*)d_out;

    float *mean, *h1, *h2;
    cudaGetSymbolAddress((void**)&mean, g_mean);
    cudaGetSymbolAddress((void**)&h1,  g_h1);
    cudaGetSymbolAddress((void**)&h2,  g_h2);
    int* deg;
    cudaGetSymbolAddress((void**)&deg, g_deg);

    const int SMEM = (64 * (DIM + 2)) * 8;  // 66560 B
    static bool attr_set = false;
    cudaFuncSetAttribute(k_gemm<true>,  cudaFuncAttributeMaxDynamicSharedMemorySize, SMEM);
    cudaFuncSetAttribute(k_gemm<false>, cudaFuncAttributeMaxDynamicSharedMemorySize, SMEM);
    (void)attr_set;

    const int NB_SCAN = (NN + 1023) / 1024;          // 98
    const int AGG_BLOCKS  = (NN * 32 + 255) / 256;   // warp per node
    const int GEMM_BLOCKS = (NN + 63) / 64;

    // CSR build
    k_zero_int<<<(NN + 255) / 256, 256>>>(deg, NN);
    k_hist<<<(NE + 255) / 256, 256>>>(dst);
    k_blocksum<<<NB_SCAN, 256>>>();
    k_bscan<<<1, 128>>>(NB_SCAN);
    k_scan_final<<<NB_SCAN, 256>>>();
    k_bucket<<<(NE + 255) / 256, 256>>>(src, dst);

    // layer 1
    k_agg<<<AGG_BLOCKS, 256>>>(x, mean);
    k_gemm<true><<<GEMM_BLOCKS, 128, SMEM>>>(mean, x, W1l, W1r, b1, h1);

    // layer 2
    k_agg<<<AGG_BLOCKS, 256>>>(h1, mean);
    k_gemm<true><<<GEMM_BLOCKS, 128, SMEM>>>(mean, h1, W2l, W2r, b2, h2);

    // layer 3 (no relu)
    k_agg<<<AGG_BLOCKS, 256>>>(h2, mean);
    k_gemm<false><<<GEMM_BLOCKS, 128, SMEM>>>(mean, h2, W3l, W3r, b3, out);
}

// round 3
// speedup vs baseline: 1.4250x; 1.1949x over previous
#include <cuda_runtime.h>
#include <cstdint>

#define NN 100000
#define NE 1600000
#define DIM 128

typedef unsigned long long u64;

// ---------------------------------------------------------------------------
// Scratch (__device__ globals: allocation-free rule)
// ---------------------------------------------------------------------------
__device__ float g_mean[NN * DIM];
__device__ float g_h1[NN * DIM];
__device__ float g_h2[NN * DIM];
__device__ int   g_deg[NN];
__device__ int   g_rowstart[NN];
__device__ int   g_cursor[NN];
__device__ int   g_csrsrc[NE];
__device__ int   g_bsum[128];

// ---------------------------------------------------------------------------
// f32x2 helpers (Blackwell packed fp32 FMA)
// ---------------------------------------------------------------------------
__device__ __forceinline__ u64 dup2(float v) {
    u64 r; asm("mov.b64 %0, {%1, %1};" : "=l"(r) : "f"(v)); return r;
}
__device__ __forceinline__ float2 unpack2(u64 v) {
    float2 p; asm("mov.b64 {%0, %1}, %2;" : "=f"(p.x), "=f"(p.y) : "l"(v)); return p;
}
__device__ __forceinline__ void ffma2(u64& d, u64 a, u64 b) {
    asm("fma.rn.f32x2 %0, %1, %2, %0;" : "+l"(d) : "l"(a), "l"(b));
}

// ---------------------------------------------------------------------------
// CSR build kernels
// ---------------------------------------------------------------------------
__global__ void k_zero_int(int* __restrict__ p, int n) {
    int i = blockIdx.x * blockDim.x + threadIdx.x;
    if (i < n) p[i] = 0;
}

__global__ void k_hist(const int* __restrict__ dst) {
    int e = blockIdx.x * blockDim.x + threadIdx.x;
    if (e < NE) atomicAdd(&g_deg[dst[e]], 1);
}

// per-1024-chunk degree sums
__global__ void k_blocksum() {
    __shared__ int sh[256];
    int base = blockIdx.x * 1024;
    int s = 0;
    for (int j = threadIdx.x; j < 1024; j += 256) {
        int i = base + j;
        if (i < NN) s += g_deg[i];
    }
    sh[threadIdx.x] = s; __syncthreads();
    for (int o = 128; o > 0; o >>= 1) {
        if (threadIdx.x < o) sh[threadIdx.x] += sh[threadIdx.x + o];
        __syncthreads();
    }
    if (threadIdx.x == 0) g_bsum[blockIdx.x] = sh[0];
}

// fused: block-base (masked sum of bsums) + local exclusive scan + write
__global__ void k_scan2() {
    __shared__ int sh[256];
    __shared__ int sbase;
    int tid = threadIdx.x;

    // base = sum of bsum[i] for i < blockIdx.x  (blockIdx.x <= 97 < 256)
    int v = (tid < blockIdx.x) ? g_bsum[tid] : 0;
    sh[tid] = v; __syncthreads();
    for (int o = 128; o > 0; o >>= 1) {
        if (tid < o) sh[tid] += sh[tid + o];
        __syncthreads();
    }
    if (tid == 0) sbase = sh[0];
    __syncthreads();

    // local exclusive scan over this block's 1024 degrees (4/thread)
    int base = blockIdx.x * 1024 + tid * 4;
    int d[4]; int s = 0;
#pragma unroll
    for (int j = 0; j < 4; ++j) {
        int i = base + j;
        d[j] = (i < NN) ? g_deg[i] : 0;
        s += d[j];
    }
    sh[tid] = s; __syncthreads();
    for (int o = 1; o < 256; o <<= 1) {
        int t = (tid >= o) ? sh[tid - o] : 0;
        __syncthreads();
        sh[tid] += t;
        __syncthreads();
    }
    int off = sbase + sh[tid] - s;
#pragma unroll
    for (int j = 0; j < 4; ++j) {
        int i = base + j;
        if (i < NN) { g_rowstart[i] = off; g_cursor[i] = off; off += d[j]; }
    }
}

__global__ void k_bucket(const int* __restrict__ src, const int* __restrict__ dst) {
    int e = blockIdx.x * blockDim.x + threadIdx.x;
    if (e < NE) {
        int pos = atomicAdd(&g_cursor[dst[e]], 1);
        g_csrsrc[pos] = src[e];
    }
}

// ---------------------------------------------------------------------------
// pull-mode mean aggregation: one warp per node, lane owns one float4 (4 dims).
// Indices read as UNIFORM per-lane LDGs (no shfl), predicated 8-wide unroll
// keeps gather MLP = 8 regardless of degree.
// ---------------------------------------------------------------------------
__global__ void __launch_bounds__(256)
k_agg(const float* __restrict__ x, float* __restrict__ mean) {
    int node = (blockIdx.x * blockDim.x + threadIdx.x) >> 5;
    int lane = threadIdx.x & 31;
    if (node >= NN) return;
    int beg = __ldg(g_rowstart + node);
    int d   = __ldg(g_deg + node);
    int end = beg + d;

    const float4* xv = (const float4*)x;
    float4 acc = make_float4(0.f, 0.f, 0.f, 0.f);

    for (int e = beg; e < end; e += 8) {
        int idx[8];
#pragma unroll
        for (int j = 0; j < 8; ++j)
            idx[j] = (e + j < end) ? __ldg(g_csrsrc + e + j) : -1;
#pragma unroll
        for (int j = 0; j < 8; ++j) {
            if (idx[j] >= 0) {
                float4 v = __ldg(xv + (size_t)idx[j] * 32 + lane);
                acc.x += v.x; acc.y += v.y; acc.z += v.z; acc.w += v.w;
            }
        }
    }
    float inv = (d > 0) ? (1.0f / (float)d) : 0.0f;
    acc.x *= inv; acc.y *= inv; acc.z *= inv; acc.w *= inv;
    ((float4*)(mean + (size_t)node * DIM))[lane] = acc;
}

// ---------------------------------------------------------------------------
// fused SAGE GEMM with packed f32x2 FMA:
//   out[n,:] = act( mean[n,:] @ Wl + hin[n,:] @ Wr + b )
//
// 128 threads = (tx 0..15 col-groups of 8) x (ty 0..7 row-groups), tile
// 64 rows x 128 cols. Raw f32 tile in smem (stride 130: 2 per-warp LDS
// addresses land in distinct banks -> 1 phase). Broadcast operand is
// duplicated to (v,v) u64 via mov.b64 on the ALU pipe, overlapping the
// FFMA2s on the FMA pipe. Weight pairs load as raw u64 LDGs (L1-resident).
// ---------------------------------------------------------------------------
template <bool RELU>
__global__ void __launch_bounds__(128, 4)
k_gemm(const float* __restrict__ mean,
       const float* __restrict__ hin,
       const float* __restrict__ Wl,
       const float* __restrict__ Wr,
       const float* __restrict__ bias,
       float* __restrict__ out) {
    constexpr int ROWS = 64;
    constexpr int STR  = DIM + 2;   // 130 floats: 8B-aligned rows, bank-distinct ty pairs
    __shared__ float s_in[ROWS * STR];

    const int tx = threadIdx.x & 15;
    const int ty = threadIdx.x >> 4;
    const int row0 = blockIdx.x * ROWS;

    u64 acc[8][4];
#pragma unroll
    for (int i = 0; i < 8; ++i)
#pragma unroll
        for (int j = 0; j < 4; ++j) acc[i][j] = 0ull;

#pragma unroll
    for (int phase = 0; phase < 2; ++phase) {
        const float* base = phase ? hin : mean;
        const float* W    = phase ? Wr  : Wl;

        __syncthreads();
        // stage 64x128 f32 tile: thread t -> (row r, float4-chunk c4)
        for (int t = threadIdx.x; t < ROWS * 32; t += 128) {
            int r  = t >> 5;
            int c4 = t & 31;
            int grow = row0 + r;
            float4 v = make_float4(0.f, 0.f, 0.f, 0.f);
            if (grow < NN)
                v = __ldg(((const float4*)(base + (size_t)grow * DIM)) + c4);
            float* p = s_in + r * STR + c4 * 4;
            *(float2*)(p)     = make_float2(v.x, v.y);
            *(float2*)(p + 2) = make_float2(v.z, v.w);
        }
        __syncthreads();

        const u64* Wp = (const u64*)W;  // Wp[k*64 + c] = (W[k][2c], W[k][2c+1])
#pragma unroll 4
        for (int k = 0; k < DIM; ++k) {
            u64 w0 = __ldg(Wp + k * 64 + tx * 4 + 0);
            u64 w1 = __ldg(Wp + k * 64 + tx * 4 + 1);
            u64 w2 = __ldg(Wp + k * 64 + tx * 4 + 2);
            u64 w3 = __ldg(Wp + k * 64 + tx * 4 + 3);
            u64 sv[8];
#pragma unroll
            for (int i = 0; i < 8; ++i) sv[i] = dup2(s_in[(ty + 8 * i) * STR + k]);
#pragma unroll
            for (int i = 0; i < 8; ++i) {
                ffma2(acc[i][0], sv[i], w0);
                ffma2(acc[i][1], sv[i], w1);
                ffma2(acc[i][2], sv[i], w2);
                ffma2(acc[i][3], sv[i], w3);
            }
        }
    }

    // epilogue
    float4 b0 = __ldg((const float4*)(bias + tx * 8));
    float4 b1 = __ldg((const float4*)(bias + tx * 8) + 1);

#pragma unroll
    for (int i = 0; i < 8; ++i) {
        int grow = row0 + ty + i * 8;
        if (grow >= NN) continue;
        float2 p0 = unpack2(acc[i][0]);
        float2 p1 = unpack2(acc[i][1]);
        float2 p2 = unpack2(acc[i][2]);
        float2 p3 = unpack2(acc[i][3]);
        float4 o0 = make_float4(p0.x + b0.x, p0.y + b0.y, p1.x + b0.z, p1.y + b0.w);
        float4 o1 = make_float4(p2.x + b1.x, p2.y + b1.y, p3.x + b1.z, p3.y + b1.w);
        if (RELU) {
            o0.x = fmaxf(o0.x, 0.f); o0.y = fmaxf(o0.y, 0.f);
            o0.z = fmaxf(o0.z, 0.f); o0.w = fmaxf(o0.w, 0.f);
            o1.x = fmaxf(o1.x, 0.f); o1.y = fmaxf(o1.y, 0.f);
            o1.z = fmaxf(o1.z, 0.f); o1.w = fmaxf(o1.w, 0.f);
        }
        float* op = out + (size_t)grow * DIM + tx * 8;
        *(float4*)(op)     = o0;
        *(float4*)(op + 4) = o1;
    }
}

// ---------------------------------------------------------------------------
// kernel_launch
// inputs: t, x, edge_index, W1_l, W1_r, b1, W2_l, W2_r, b2, W3_l, W3_r, b3
// launch order puts k_agg (layer 1) at launch index 5 for ncu (-s 5 -c 1).
// ---------------------------------------------------------------------------
extern "C" void kernel_launch(void* const* d_in, const int* in_sizes, int n_in,
                              void* d_out, int out_size) {
    const float* x   = (const float*)d_in[1];
    const int*   ei  = (const int*)d_in[2];
    const int*   src = ei;
    const int*   dst = ei + NE;
    const float* W1l = (const float*)d_in[3];
    const float* W1r = (const float*)d_in[4];
    const float* b1  = (const float*)d_in[5];
    const float* W2l = (const float*)d_in[6];
    const float* W2r = (const float*)d_in[7];
    const float* b2  = (const float*)d_in[8];
    const float* W3l = (const float*)d_in[9];
    const float* W3r = (const float*)d_in[10];
    const float* b3  = (const float*)d_in[11];
    float* out = (float*)d_out;

    float *mean, *h1, *h2;
    cudaGetSymbolAddress((void**)&mean, g_mean);
    cudaGetSymbolAddress((void**)&h1,  g_h1);
    cudaGetSymbolAddress((void**)&h2,  g_h2);
    int* deg;
    cudaGetSymbolAddress((void**)&deg, g_deg);

    const int NB_SCAN     = (NN + 1023) / 1024;        // 98
    const int AGG_BLOCKS  = (NN * 32 + 255) / 256;
    const int GEMM_BLOCKS = (NN + 63) / 64;

    // CSR build (launches 0-4)
    k_zero_int<<<(NN + 255) / 256, 256>>>(deg, NN);
    k_hist<<<(NE + 255) / 256, 256>>>(dst);
    k_blocksum<<<NB_SCAN, 256>>>();
    k_scan2<<<NB_SCAN, 256>>>();
    k_bucket<<<(NE + 255) / 256, 256>>>(src, dst);

    // layer 1 (k_agg = launch index 5 -> ncu target)
    k_agg<<<AGG_BLOCKS, 256>>>(x, mean);
    k_gemm<true><<<GEMM_BLOCKS, 128>>>(mean, x, W1l, W1r, b1, h1);

    // layer 2
    k_agg<<<AGG_BLOCKS, 256>>>(h1, mean);
    k_gemm<true><<<GEMM_BLOCKS, 128>>>(mean, h1, W2l, W2r, b2, h2);

    // layer 3 (no relu)
    k_agg<<<AGG_BLOCKS, 256>>>(h2, mean);
    k_gemm<false><<<GEMM_BLOCKS, 128>>>(mean, h2, W3l, W3r, b3, out);
}